// round 12
// baseline (speedup 1.0000x reference)
#include <cuda_runtime.h>
#include <cuda_bf16.h>

// Problem constants
#define HH 128
#define WW 128
#define NN (HH*WW)          // 16384 nodes per batch
#define EE (2*NN)           // 32768 edges per batch
#define BB 2
#define NBUCK 4096
#define WWIN 1024           // filter window (1 edge per thread)
#define FULLM 0xffffffffu

// ---------------- device globals (no allocation allowed) ----------------
__device__ unsigned long long g_sorted[BB][EE];   // (aff_bits<<32)|edge_idx, ascending
__device__ double g_loss[BB];

// Shared layout (dynamic), u32 first:
//   u32 info [NN]        64KB  (size | nz<<16)
//   u32 hist [NBUCK]     16KB  (sort cursors, then claim table)
//   u32 offs [NBUCK+1]   16KB
//   u32 warp_sums[32], labcnt[64], misc[4]
//   u32 caff  [WWIN]      4KB  (compacted candidate affinities)
//   u32 croots[WWIN]      4KB  (compacted candidate roots, ru|rv<<16)
//   u16 parent[NN]       32KB
#define SMEM_BYTES ((NN + NBUCK + (NBUCK+1) + 32 + 64 + 4 + WWIN + WWIN) * 4 + NN * 2)

extern __shared__ unsigned char smem_raw[];

__global__ void __launch_bounds__(1024) malis_kernel(const float* __restrict__ aff,
                                                     const void* __restrict__ gt) {
    int b    = blockIdx.x;
    int tid  = threadIdx.x;
    int lane = tid & 31;
    int wid  = tid >> 5;

    unsigned* info      = (unsigned*)smem_raw;
    unsigned* hist      = info + NN;
    unsigned* offs      = hist + NBUCK;
    unsigned* warp_sums = offs + NBUCK + 1;
    unsigned* labcnt    = warp_sums + 32;
    unsigned* misc      = labcnt + 64;           // [0]=detect/done  [1]=ncand
    unsigned* caff      = misc + 4;
    unsigned* croots    = caff + WWIN;
    unsigned short* parent = (unsigned short*)(croots + WWIN);

    // ---- detect int64 vs int32 groundtruth (labels < 64 -> odd words zero) ----
    if (tid == 0) misc[0] = 0;
    for (int i = tid; i < 64; i += 1024) labcnt[i] = 0;
    __syncthreads();
    {
        const int* g32 = (const int*)gt;
        if (g32[2 * tid + 1]) atomicOr(&misc[0], 1u);
    }
    __syncthreads();
    int is64 = (misc[0] == 0);

    // ---- init union-find + label histogram ----
    for (int n = tid; n < NN; n += 1024) {
        int l = is64 ? (int)((const long long*)gt)[b * NN + n]
                     : ((const int*)gt)[b * NN + n];
        parent[n] = (unsigned short)n;
        info[n]   = 1u | ((l != 0) ? (1u << 16) : 0u);
        if (l) atomicAdd(&labcnt[l], 1u);
    }

    // ---- bucket sort of edges (ascending by (aff_bits, idx)) ----
    const float* a = aff + b * EE;
    for (int i = tid; i < NBUCK; i += 1024) hist[i] = 0;
    __syncthreads();

    for (int e = tid; e < EE; e += 1024) {
        int bk = min(NBUCK - 1, (int)(a[e] * (float)NBUCK));
        atomicAdd(&hist[bk], 1u);
    }
    __syncthreads();

    // exclusive scan of hist[4096], 4 buckets per thread
    unsigned s0 = hist[4*tid], s1 = hist[4*tid+1], s2 = hist[4*tid+2], s3 = hist[4*tid+3];
    unsigned tsum = s0 + s1 + s2 + s3;
    unsigned inc = tsum;
    #pragma unroll
    for (int o = 1; o < 32; o <<= 1) {
        unsigned v = __shfl_up_sync(FULLM, inc, o);
        if (lane >= o) inc += v;
    }
    if (lane == 31) warp_sums[wid] = inc;
    __syncthreads();
    if (tid < 32) {
        unsigned v = warp_sums[tid];
        unsigned iv = v;
        #pragma unroll
        for (int o = 1; o < 32; o <<= 1) {
            unsigned t2 = __shfl_up_sync(FULLM, iv, o);
            if (tid >= o) iv += t2;
        }
        warp_sums[tid] = iv - v;  // exclusive warp base
    }
    __syncthreads();
    unsigned base0 = warp_sums[wid] + inc - tsum;
    offs[4*tid]   = base0;
    offs[4*tid+1] = base0 + s0;
    offs[4*tid+2] = base0 + s0 + s1;
    offs[4*tid+3] = base0 + s0 + s1 + s2;
    __syncthreads();
    for (int i = tid; i < NBUCK; i += 1024) hist[i] = offs[i];  // scatter cursors
    if (tid == 0) offs[NBUCK] = EE;
    __syncthreads();

    unsigned long long* arr = g_sorted[b];
    for (int e = tid; e < EE; e += 1024) {
        float av = a[e];
        int bk = min(NBUCK - 1, (int)(av * (float)NBUCK));
        unsigned pos = atomicAdd(&hist[bk], 1u);
        arr[pos] = ((unsigned long long)__float_as_uint(av) << 32) | (unsigned)e;
    }
    __syncthreads();

    // reset hist -> claim table for the resolve phase
    for (int i = tid; i < NBUCK; i += 1024) hist[i] = 0;

    // per-bucket insertion sort (ascending)
    for (int bk = tid; bk < NBUCK; bk += 1024) {
        int s = (int)offs[bk], epos = (int)offs[bk + 1];
        for (int k = s + 1; k < epos; k++) {
            unsigned long long key = arr[k];
            int j = k - 1;
            while (j >= s && arr[j] > key) { arr[j + 1] = arr[j]; j--; }
            arr[j + 1] = key;
        }
    }
    if (tid == 0) misc[0] = 0;   // done flag
    __syncthreads();

    // ==== windowed Kruskal: block-parallel filter + warp-0 compacted resolve ====
    // per-merge contribution: tu*tv*a   (n_pos telescopes to sum_l C(n_l,2))
    double acc = 0.0;       // meaningful in warp 0 lanes
    int nmerges = 0;        // warp-uniform in warp 0 (derived from ballots)

    for (int wbase = EE - WWIN; wbase >= 0; wbase -= WWIN) {
        // ---- filter: 1 edge per thread, finds with path halving (forest static) ----
        unsigned long long pk = arr[wbase + tid];
        unsigned idx = (unsigned)pk;
        int c  = (int)(idx >> 14);
        int uu = (int)(idx & (NN - 1));
        int vv = (c == 0) ? ((uu < NN - WW) ? uu + WW : -1)
                          : (((uu & (WW - 1)) != WW - 1) ? uu + 1 : -1);
        int ru = 0, rv = 0;
        bool cnd = false;
        if (vv >= 0) {
            int x = uu, p = parent[x];
            while (p != x) {
                int g2 = parent[p];
                parent[x] = (unsigned short)g2;
                x = g2; p = parent[x];
            }
            ru = x;
            x = vv; p = parent[x];
            while (p != x) {
                int g2 = parent[p];
                parent[x] = (unsigned short)g2;
                x = g2; p = parent[x];
            }
            rv = x;
            cnd = (ru != rv);
        }
        unsigned wmask = __ballot_sync(FULLM, cnd);
        if (lane == 0) warp_sums[wid] = __popc(wmask);
        __syncthreads();
        if (tid < 32) {
            unsigned v = warp_sums[tid], iv = v;
            #pragma unroll
            for (int o = 1; o < 32; o <<= 1) {
                unsigned t2 = __shfl_up_sync(FULLM, iv, o);
                if (tid >= o) iv += t2;
            }
            warp_sums[tid] = iv - v;
            if (tid == 31) misc[1] = iv;   // ncand
        }
        __syncthreads();
        int ncand = (int)misc[1];
        if (cnd) {
            int r = (int)warp_sums[wid] + __popc(wmask & ((1u << lane) - 1));
            croots[r] = (unsigned)ru | ((unsigned)rv << 16);
            caff[r]   = (unsigned)(pk >> 32);
        }
        __syncthreads();

        // ---- resolve: warp 0 only, descending affinity = descending rank ----
        if (wid == 0 && ncand) {
            for (int cb = 0; cb < ncand; cb += 32) {
                int j = ncand - 1 - cb - lane;   // lane 0 = highest affinity in chunk
                bool active = (j >= 0);
                int rru = 0, rrv = 0;
                unsigned ab = 0;
                if (active) {
                    unsigned pr = croots[j];
                    rru = (int)(pr & 0xffffu);
                    rrv = (int)(pr >> 16);
                    ab  = caff[j];
                }

                // iterative parallel claim-retry (no serial fallback)
                for (;;) {
                    if (active) {
                        int p = parent[rru];
                        while (p != rru) { rru = p; p = parent[rru]; }
                        p = parent[rrv];
                        while (p != rrv) { rrv = p; p = parent[rrv]; }
                        active = (rru != rrv);
                    }
                    unsigned cand = __ballot_sync(FULLM, active);
                    if (!cand) break;

                    bool claimed = active;
                    unsigned prio = 32u - (unsigned)lane;   // lane 0 = highest
                    unsigned h1 = 0, h2 = 0;
                    if (claimed) {
                        h1 = (unsigned)rru & (NBUCK - 1);
                        h2 = (unsigned)rrv & (NBUCK - 1);
                        atomicMax(&hist[h1], prio);
                        atomicMax(&hist[h2], prio);
                    }
                    __syncwarp(FULLM);
                    bool par = claimed && (hist[h1] == prio) && (hist[h2] == prio);
                    unsigned parmask = __ballot_sync(FULLM, par);

                    if (par) {   // conflict-free winners merge concurrently
                        unsigned iu = info[rru], iv2 = info[rrv];
                        int su = (int)(iu & 0xffffu), sv = (int)(iv2 & 0xffffu);
                        acc += (double)((int)(iu >> 16) * (int)(iv2 >> 16))
                             * (double)__uint_as_float(ab);
                        int big   = (su >= sv) ? rru : rrv;
                        int small = rru + rrv - big;
                        parent[small] = (unsigned short)big;
                        info[big] = iu + iv2;   // packed u16 adds, no carry (<=16384)
                        active = false;         // done with this edge
                    }
                    __syncwarp(FULLM);
                    nmerges += __popc(parmask);

                    if (claimed) { hist[h1] = 0; hist[h2] = 0; }  // reset claim slots
                    __syncwarp(FULLM);

                    if (nmerges == NN - 1) break;   // MST complete (warp-uniform)
                }

                if (nmerges == NN - 1) {
                    if (lane == 0) misc[0] = 1;
                    break;
                }
            }
        }
        __syncthreads();
        if (misc[0]) break;   // remaining edges contribute 0
    }

    // ---- final reduction (warp 0) ----
    if (wid == 0) {
        #pragma unroll
        for (int o = 16; o; o >>= 1)
            acc += __shfl_down_sync(FULLM, acc, o);
        if (lane == 0) {
            unsigned long long pairs = 0;
            for (int l = 1; l < 64; l++) {
                unsigned long long n = labcnt[l];
                pairs += n * (n - 1) / 2;
            }
            g_loss[b] = 0.5 * ((double)pairs - acc);
        }
    }
}

__global__ void finalize_kernel(float* out) {
    out[0] = (float)(g_loss[0] + g_loss[1]);
}

// ---------------- launch -------------------------------------------------
extern "C" void kernel_launch(void* const* d_in, const int* in_sizes, int n_in,
                              void* d_out, int out_size) {
    const float* aff = (const float*)d_in[0];
    const void*  gt  = d_in[1];
    (void)in_sizes; (void)n_in; (void)out_size;

    cudaFuncSetAttribute(malis_kernel,
                         cudaFuncAttributeMaxDynamicSharedMemorySize, SMEM_BYTES);
    malis_kernel<<<BB, 1024, SMEM_BYTES>>>(aff, gt);
    finalize_kernel<<<1, 1>>>((float*)d_out);
}

// round 13
// speedup vs baseline: 1.2143x; 1.2143x over previous
#include <cuda_runtime.h>
#include <cuda_bf16.h>

// Problem constants
#define HH 128
#define WW 128
#define NN (HH*WW)          // 16384 nodes per batch
#define EE (2*NN)           // 32768 edges per batch
#define BB 2
#define NBUCK 4096
#define WWIN 1024           // filter window (1 edge per thread)
#define FULLM 0xffffffffu

// ---------------- device globals (no allocation allowed) ----------------
__device__ unsigned long long g_sorted[BB][EE];   // (aff_bits<<32)|edge_idx, ascending
__device__ double g_loss[BB];

// Shared layout (dynamic), u32 first:
//   u32 info [NN]        64KB  (size | nz<<16)
//   u32 hist [NBUCK]     16KB  (sort cursors, then claim table)
//   u32 offs [NBUCK+1]   16KB
//   u32 warp_sums[32], labcnt[64], misc[4]
//   u32 caff  [WWIN]      4KB  (compacted candidate affinities)
//   u32 croots[WWIN]      4KB  (compacted candidate roots, ru|rv<<16)
//   u16 parent[NN]       32KB
#define SMEM_BYTES ((NN + NBUCK + (NBUCK+1) + 32 + 64 + 4 + WWIN + WWIN) * 4 + NN * 2)

extern __shared__ unsigned char smem_raw[];

__global__ void __launch_bounds__(1024) malis_kernel(const float* __restrict__ aff,
                                                     const void* __restrict__ gt) {
    int b    = blockIdx.x;
    int tid  = threadIdx.x;
    int lane = tid & 31;
    int wid  = tid >> 5;

    unsigned* info      = (unsigned*)smem_raw;
    unsigned* hist      = info + NN;
    unsigned* offs      = hist + NBUCK;
    unsigned* warp_sums = offs + NBUCK + 1;
    unsigned* labcnt    = warp_sums + 32;
    unsigned* misc      = labcnt + 64;           // [0]=detect/done  [1]=ncand
    unsigned* caff      = misc + 4;
    unsigned* croots    = caff + WWIN;
    unsigned short* parent = (unsigned short*)(croots + WWIN);

    // ---- detect int64 vs int32 groundtruth (labels < 64 -> odd words zero) ----
    if (tid == 0) misc[0] = 0;
    for (int i = tid; i < 64; i += 1024) labcnt[i] = 0;
    __syncthreads();
    {
        const int* g32 = (const int*)gt;
        if (g32[2 * tid + 1]) atomicOr(&misc[0], 1u);
    }
    __syncthreads();
    int is64 = (misc[0] == 0);

    // ---- init union-find + label histogram ----
    for (int n = tid; n < NN; n += 1024) {
        int l = is64 ? (int)((const long long*)gt)[b * NN + n]
                     : ((const int*)gt)[b * NN + n];
        parent[n] = (unsigned short)n;
        info[n]   = 1u | ((l != 0) ? (1u << 16) : 0u);
        if (l) atomicAdd(&labcnt[l], 1u);
    }

    // ---- bucket sort of edges (ascending by (aff_bits, idx)) ----
    const float* a = aff + b * EE;
    for (int i = tid; i < NBUCK; i += 1024) hist[i] = 0;
    __syncthreads();

    for (int e = tid; e < EE; e += 1024) {
        int bk = min(NBUCK - 1, (int)(a[e] * (float)NBUCK));
        atomicAdd(&hist[bk], 1u);
    }
    __syncthreads();

    // exclusive scan of hist[4096], 4 buckets per thread
    unsigned s0 = hist[4*tid], s1 = hist[4*tid+1], s2 = hist[4*tid+2], s3 = hist[4*tid+3];
    unsigned tsum = s0 + s1 + s2 + s3;
    unsigned inc = tsum;
    #pragma unroll
    for (int o = 1; o < 32; o <<= 1) {
        unsigned v = __shfl_up_sync(FULLM, inc, o);
        if (lane >= o) inc += v;
    }
    if (lane == 31) warp_sums[wid] = inc;
    __syncthreads();
    if (tid < 32) {
        unsigned v = warp_sums[tid];
        unsigned iv = v;
        #pragma unroll
        for (int o = 1; o < 32; o <<= 1) {
            unsigned t2 = __shfl_up_sync(FULLM, iv, o);
            if (tid >= o) iv += t2;
        }
        warp_sums[tid] = iv - v;  // exclusive warp base
    }
    __syncthreads();
    unsigned base0 = warp_sums[wid] + inc - tsum;
    offs[4*tid]   = base0;
    offs[4*tid+1] = base0 + s0;
    offs[4*tid+2] = base0 + s0 + s1;
    offs[4*tid+3] = base0 + s0 + s1 + s2;
    __syncthreads();
    for (int i = tid; i < NBUCK; i += 1024) hist[i] = offs[i];  // scatter cursors
    if (tid == 0) offs[NBUCK] = EE;
    __syncthreads();

    unsigned long long* arr = g_sorted[b];
    for (int e = tid; e < EE; e += 1024) {
        float av = a[e];
        int bk = min(NBUCK - 1, (int)(av * (float)NBUCK));
        unsigned pos = atomicAdd(&hist[bk], 1u);
        arr[pos] = ((unsigned long long)__float_as_uint(av) << 32) | (unsigned)e;
    }
    __syncthreads();

    // reset hist -> claim table for the resolve phase
    for (int i = tid; i < NBUCK; i += 1024) hist[i] = 0;

    // per-bucket insertion sort (ascending)
    for (int bk = tid; bk < NBUCK; bk += 1024) {
        int s = (int)offs[bk], epos = (int)offs[bk + 1];
        for (int k = s + 1; k < epos; k++) {
            unsigned long long key = arr[k];
            int j = k - 1;
            while (j >= s && arr[j] > key) { arr[j + 1] = arr[j]; j--; }
            arr[j + 1] = key;
        }
    }
    if (tid == 0) misc[0] = 0;   // done flag
    __syncthreads();

    // ==== windowed Kruskal: block-parallel filter + warp-0 compacted resolve ====
    // per-merge contribution: tu*tv*a   (n_pos telescopes to sum_l C(n_l,2))
    double acc = 0.0;       // meaningful in warp 0 lanes
    int nmerges = 0;        // warp-uniform in warp 0

    for (int wbase = EE - WWIN; wbase >= 0; wbase -= WWIN) {
        // ---- filter: 1 edge per thread, finds with path halving (forest static) ----
        unsigned long long pk = arr[wbase + tid];
        unsigned idx = (unsigned)pk;
        int c  = (int)(idx >> 14);
        int uu = (int)(idx & (NN - 1));
        int vv = (c == 0) ? ((uu < NN - WW) ? uu + WW : -1)
                          : (((uu & (WW - 1)) != WW - 1) ? uu + 1 : -1);
        int ru = 0, rv = 0;
        bool cnd = false;
        if (vv >= 0) {
            int x = uu, p = parent[x];
            while (p != x) {
                int g2 = parent[p];
                parent[x] = (unsigned short)g2;
                x = g2; p = parent[x];
            }
            ru = x;
            x = vv; p = parent[x];
            while (p != x) {
                int g2 = parent[p];
                parent[x] = (unsigned short)g2;
                x = g2; p = parent[x];
            }
            rv = x;
            cnd = (ru != rv);
        }
        unsigned wmask = __ballot_sync(FULLM, cnd);
        if (lane == 0) warp_sums[wid] = __popc(wmask);
        __syncthreads();
        if (tid < 32) {
            unsigned v = warp_sums[tid], iv = v;
            #pragma unroll
            for (int o = 1; o < 32; o <<= 1) {
                unsigned t2 = __shfl_up_sync(FULLM, iv, o);
                if (tid >= o) iv += t2;
            }
            warp_sums[tid] = iv - v;
            if (tid == 31) misc[1] = iv;   // ncand
        }
        __syncthreads();
        int ncand = (int)misc[1];
        if (cnd) {
            int r = (int)warp_sums[wid] + __popc(wmask & ((1u << lane) - 1));
            croots[r] = (unsigned)ru | ((unsigned)rv << 16);
            caff[r]   = (unsigned)(pk >> 32);
        }
        __syncthreads();

        // ---- resolve: warp 0 only, descending affinity = descending rank ----
        if (wid == 0 && ncand) {
            for (int cb = 0; cb < ncand; cb += 32) {
                int j = ncand - 1 - cb - lane;   // lane 0 = highest affinity in chunk
                bool has = (j >= 0);
                int rru = 0, rrv = 0;
                unsigned ab = 0;
                if (has) {
                    unsigned pr = croots[j];
                    rru = (int)(pr & 0xffffu);
                    rrv = (int)(pr >> 16);
                    ab  = caff[j];
                    // re-climb to current roots (filter roots already compressed)
                    int p = parent[rru];
                    while (p != rru) { rru = p; p = parent[rru]; }
                    p = parent[rrv];
                    while (p != rrv) { rrv = p; p = parent[rrv]; }
                }
                bool cc = has && (rru != rrv);
                unsigned cand = __ballot_sync(FULLM, cc);
                if (!cand) continue;

                // ---- fast path: single candidate -> no conflicts possible ----
                if (__popc(cand) == 1) {
                    if (cc) {
                        unsigned iu = info[rru], iv2 = info[rrv];
                        int su = (int)(iu & 0xffffu), sv = (int)(iv2 & 0xffffu);
                        acc += (double)((int)(iu >> 16) * (int)(iv2 >> 16))
                             * (double)__uint_as_float(ab);
                        int big   = (su >= sv) ? rru : rrv;
                        int small = rru + rrv - big;
                        parent[small] = (unsigned short)big;
                        info[big] = iu + iv2;
                    }
                    __syncwarp(FULLM);
                    nmerges += 1;
                    if (nmerges == NN - 1) {
                        if (lane == 0) misc[0] = 1;
                        break;
                    }
                    continue;
                }

                unsigned prio = 32u - (unsigned)lane;   // higher = higher affinity
                unsigned h1 = 0, h2 = 0;
                if (cc) {
                    h1 = (unsigned)rru & (NBUCK - 1);
                    h2 = (unsigned)rrv & (NBUCK - 1);
                    atomicMax(&hist[h1], prio);
                    atomicMax(&hist[h2], prio);
                }
                __syncwarp(FULLM);
                bool par = cc && (hist[h1] == prio) && (hist[h2] == prio);
                unsigned parmask = __ballot_sync(FULLM, par);

                if (par) {   // conflict-free winners merge concurrently
                    unsigned iu = info[rru], iv2 = info[rrv];
                    int su = (int)(iu & 0xffffu), sv = (int)(iv2 & 0xffffu);
                    acc += (double)((int)(iu >> 16) * (int)(iv2 >> 16))
                         * (double)__uint_as_float(ab);
                    int big   = (su >= sv) ? rru : rrv;
                    int small = rru + rrv - big;
                    parent[small] = (unsigned short)big;
                    info[big] = iu + iv2;   // packed u16 adds, no carry (<=16384)
                }
                // deferred lanes publish their fresh roots for lane 0's smem reads
                if (cc && !par) croots[j] = (unsigned)rru | ((unsigned)rrv << 16);
                __syncwarp(FULLM);
                nmerges += __popc(parmask);

                // serial fallback: lane 0, smem-based, descending affinity order
                unsigned def = cand & ~parmask;
                int sm = 0;
                if (lane == 0) {
                    unsigned d = def;
                    while (d) {
                        int i = __ffs(d) - 1;      // ascending lane = descending aff
                        d &= d - 1;
                        int jj = ncand - 1 - cb - i;
                        unsigned pr = croots[jj];
                        unsigned ab2 = caff[jj];
                        int au = (int)(pr & 0xffffu);
                        int av = (int)(pr >> 16);
                        int p = parent[au];
                        while (p != au) { au = p; p = parent[au]; }
                        p = parent[av];
                        while (p != av) { av = p; p = parent[av]; }
                        if (au != av) {
                            unsigned iu = info[au], iv2 = info[av];
                            int su = (int)(iu & 0xffffu), sv = (int)(iv2 & 0xffffu);
                            acc += (double)((int)(iu >> 16) * (int)(iv2 >> 16))
                                 * (double)__uint_as_float(ab2);
                            int big   = (su >= sv) ? au : av;
                            int small = au + av - big;
                            parent[small] = (unsigned short)big;
                            info[big] = iu + iv2;
                            sm++;
                        }
                    }
                }
                nmerges += __shfl_sync(FULLM, sm, 0);

                if (cc) { hist[h1] = 0; hist[h2] = 0; }   // reset claim slots
                __syncwarp(FULLM);

                if (nmerges == NN - 1) {                  // MST complete
                    if (lane == 0) misc[0] = 1;
                    break;
                }
            }
        }
        __syncthreads();
        if (misc[0]) break;   // remaining edges contribute 0
    }

    // ---- final reduction (warp 0) ----
    if (wid == 0) {
        #pragma unroll
        for (int o = 16; o; o >>= 1)
            acc += __shfl_down_sync(FULLM, acc, o);
        if (lane == 0) {
            unsigned long long pairs = 0;
            for (int l = 1; l < 64; l++) {
                unsigned long long n = labcnt[l];
                pairs += n * (n - 1) / 2;
            }
            g_loss[b] = 0.5 * ((double)pairs - acc);
        }
    }
}

__global__ void finalize_kernel(float* out) {
    out[0] = (float)(g_loss[0] + g_loss[1]);
}

// ---------------- launch -------------------------------------------------
extern "C" void kernel_launch(void* const* d_in, const int* in_sizes, int n_in,
                              void* d_out, int out_size) {
    const float* aff = (const float*)d_in[0];
    const void*  gt  = d_in[1];
    (void)in_sizes; (void)n_in; (void)out_size;

    cudaFuncSetAttribute(malis_kernel,
                         cudaFuncAttributeMaxDynamicSharedMemorySize, SMEM_BYTES);
    malis_kernel<<<BB, 1024, SMEM_BYTES>>>(aff, gt);
    finalize_kernel<<<1, 1>>>((float*)d_out);
}

// round 14
// speedup vs baseline: 1.2182x; 1.0032x over previous
#include <cuda_runtime.h>
#include <cuda_bf16.h>

// Problem constants
#define HH 128
#define WW 128
#define NN (HH*WW)          // 16384 nodes per batch
#define EE (2*NN)           // 32768 edges per batch
#define BB 2
#define NBUCK 4096
#define WWIN 1024           // filter window (1 edge per thread)
#define NDEDUP 2048         // u64 dedupe slots (reuses offs region, 16KB)
#define FULLM 0xffffffffu

// ---------------- device globals (no allocation allowed) ----------------
__device__ unsigned long long g_sorted[BB][EE];   // (aff_bits<<32)|edge_idx, ascending
__device__ double g_loss[BB];

// Shared layout (dynamic), u32 first:
//   u32 info [NN]        64KB  (size | nz<<16)
//   u32 hist [NBUCK]     16KB  (sort cursors, then claim table)
//   u32 offs [NBUCK+1]   16KB  (sort offsets, then u64 dedupe table)
//   u32 warp_sums[32], labcnt[64], misc[4]
//   u32 caff  [WWIN]      4KB  (compacted candidate affinities)
//   u32 croots[WWIN]      4KB  (compacted candidate roots, ru|rv<<16)
//   u16 parent[NN]       32KB
#define SMEM_BYTES ((NN + NBUCK + (NBUCK+1+1) + 32 + 64 + 4 + WWIN + WWIN) * 4 + NN * 2)

extern __shared__ unsigned char smem_raw[];

__global__ void __launch_bounds__(1024) malis_kernel(const float* __restrict__ aff,
                                                     const void* __restrict__ gt) {
    int b    = blockIdx.x;
    int tid  = threadIdx.x;
    int lane = tid & 31;
    int wid  = tid >> 5;

    unsigned* info      = (unsigned*)smem_raw;
    unsigned* hist      = info + NN;
    unsigned* offs      = hist + NBUCK;                 // also dedupe table (u64)
    unsigned* warp_sums = offs + NBUCK + 2;
    unsigned* labcnt    = warp_sums + 32;
    unsigned* misc      = labcnt + 64;                  // [0]=detect/done  [1]=ncand
    unsigned* caff      = misc + 4;
    unsigned* croots    = caff + WWIN;
    unsigned short* parent = (unsigned short*)(croots + WWIN);
    unsigned long long* dedup = (unsigned long long*)offs;   // 2048 slots

    // ---- detect int64 vs int32 groundtruth (labels < 64 -> odd words zero) ----
    if (tid == 0) misc[0] = 0;
    for (int i = tid; i < 64; i += 1024) labcnt[i] = 0;
    __syncthreads();
    {
        const int* g32 = (const int*)gt;
        if (g32[2 * tid + 1]) atomicOr(&misc[0], 1u);
    }
    __syncthreads();
    int is64 = (misc[0] == 0);

    // ---- init union-find + label histogram ----
    for (int n = tid; n < NN; n += 1024) {
        int l = is64 ? (int)((const long long*)gt)[b * NN + n]
                     : ((const int*)gt)[b * NN + n];
        parent[n] = (unsigned short)n;
        info[n]   = 1u | ((l != 0) ? (1u << 16) : 0u);
        if (l) atomicAdd(&labcnt[l], 1u);
    }

    // ---- bucket sort of edges (ascending by (aff_bits, idx)) ----
    const float* a = aff + b * EE;
    for (int i = tid; i < NBUCK; i += 1024) hist[i] = 0;
    __syncthreads();

    for (int e = tid; e < EE; e += 1024) {
        int bk = min(NBUCK - 1, (int)(a[e] * (float)NBUCK));
        atomicAdd(&hist[bk], 1u);
    }
    __syncthreads();

    // exclusive scan of hist[4096], 4 buckets per thread
    unsigned s0 = hist[4*tid], s1 = hist[4*tid+1], s2 = hist[4*tid+2], s3 = hist[4*tid+3];
    unsigned tsum = s0 + s1 + s2 + s3;
    unsigned inc = tsum;
    #pragma unroll
    for (int o = 1; o < 32; o <<= 1) {
        unsigned v = __shfl_up_sync(FULLM, inc, o);
        if (lane >= o) inc += v;
    }
    if (lane == 31) warp_sums[wid] = inc;
    __syncthreads();
    if (tid < 32) {
        unsigned v = warp_sums[tid];
        unsigned iv = v;
        #pragma unroll
        for (int o = 1; o < 32; o <<= 1) {
            unsigned t2 = __shfl_up_sync(FULLM, iv, o);
            if (tid >= o) iv += t2;
        }
        warp_sums[tid] = iv - v;  // exclusive warp base
    }
    __syncthreads();
    unsigned base0 = warp_sums[wid] + inc - tsum;
    // stash scan results; offs region will be reused but is needed for sort first
    offs[4*tid]   = base0;
    offs[4*tid+1] = base0 + s0;
    offs[4*tid+2] = base0 + s0 + s1;
    offs[4*tid+3] = base0 + s0 + s1 + s2;
    __syncthreads();
    for (int i = tid; i < NBUCK; i += 1024) hist[i] = offs[i];  // scatter cursors
    if (tid == 0) offs[NBUCK] = EE;
    __syncthreads();

    unsigned long long* arr = g_sorted[b];
    for (int e = tid; e < EE; e += 1024) {
        float av = a[e];
        int bk = min(NBUCK - 1, (int)(av * (float)NBUCK));
        unsigned pos = atomicAdd(&hist[bk], 1u);
        arr[pos] = ((unsigned long long)__float_as_uint(av) << 32) | (unsigned)e;
    }
    __syncthreads();

    // per-bucket insertion sort (ascending); save bounds in registers first
    {
        unsigned my_off[4], nxt_off[4];
        #pragma unroll
        for (int q = 0; q < 4; q++) {
            int bk = tid + q * 1024;
            my_off[q] = offs[bk];
            nxt_off[q] = offs[bk + 1];
        }
        __syncthreads();
        #pragma unroll
        for (int q = 0; q < 4; q++) {
            int s = (int)my_off[q], epos = (int)nxt_off[q];
            for (int k = s + 1; k < epos; k++) {
                unsigned long long key = arr[k];
                int j = k - 1;
                while (j >= s && arr[j] > key) { arr[j + 1] = arr[j]; j--; }
                arr[j + 1] = key;
            }
        }
    }

    // reset hist -> claim table; offs -> dedupe table
    for (int i = tid; i < NBUCK; i += 1024) hist[i] = 0;
    for (int i = tid; i < NDEDUP; i += 1024) dedup[i] = 0ull;
    if (tid == 0) misc[0] = 0;   // done flag
    __syncthreads();

    // ==== windowed Kruskal: filter + dedupe + warp-0 compacted resolve ====
    // per-merge contribution: tu*tv*a   (n_pos telescopes to sum_l C(n_l,2))
    double acc = 0.0;       // meaningful in warp 0 lanes
    int nmerges = 0;        // warp-uniform in warp 0

    for (int wbase = EE - WWIN; wbase >= 0; wbase -= WWIN) {
        // ---- filter: 1 edge per thread, finds with path halving (forest static) ----
        unsigned long long pk = arr[wbase + tid];
        unsigned idx = (unsigned)pk;
        unsigned abits = (unsigned)(pk >> 32);
        int c  = (int)(idx >> 14);
        int uu = (int)(idx & (NN - 1));
        int vv = (c == 0) ? ((uu < NN - WW) ? uu + WW : -1)
                          : (((uu & (WW - 1)) != WW - 1) ? uu + 1 : -1);
        int ru = 0, rv = 0;
        bool cnd = false;
        if (vv >= 0) {
            int x = uu, p = parent[x];
            while (p != x) {
                int g2 = parent[p];
                parent[x] = (unsigned short)g2;
                x = g2; p = parent[x];
            }
            ru = x;
            x = vv; p = parent[x];
            while (p != x) {
                int g2 = parent[p];
                parent[x] = (unsigned short)g2;
                x = g2; p = parent[x];
            }
            rv = x;
            cnd = (ru != rv);
        }

        // ---- dedupe identical root pairs: keep highest-affinity edge only ----
        unsigned key = 0, slot = 0;
        unsigned long long rec = 0;
        if (cnd) {
            int rmin = min(ru, rv), rmax = max(ru, rv);
            key  = (unsigned)rmin | ((unsigned)rmax << 14);       // 28 bits
            slot = (key * 2654435761u) >> 21;                     // 11 bits
            rec  = ((unsigned long long)abits << 32) | key;
            atomicMax(&dedup[slot], rec);
        }
        __syncthreads();
        if (cnd) {
            unsigned long long t = dedup[slot];
            // survive if I'm the pair's max, or a different pair owns the slot
            cnd = (t == rec) || ((unsigned)(t & 0xfffffffu) != key);
        }
        unsigned wmask = __ballot_sync(FULLM, cnd);
        if (lane == 0) warp_sums[wid] = __popc(wmask);
        __syncthreads();
        // clear touched dedupe slots (safe: all survival reads done)
        if (rec) dedup[slot] = 0ull;
        if (tid < 32) {
            unsigned v = warp_sums[tid], iv = v;
            #pragma unroll
            for (int o = 1; o < 32; o <<= 1) {
                unsigned t2 = __shfl_up_sync(FULLM, iv, o);
                if (tid >= o) iv += t2;
            }
            warp_sums[tid] = iv - v;
            if (tid == 31) misc[1] = iv;   // ncand
        }
        __syncthreads();
        int ncand = (int)misc[1];
        if (cnd) {
            int r = (int)warp_sums[wid] + __popc(wmask & ((1u << lane) - 1));
            croots[r] = (unsigned)ru | ((unsigned)rv << 16);
            caff[r]   = abits;
        }
        __syncthreads();

        // ---- resolve: warp 0 only, descending affinity = descending rank ----
        if (wid == 0 && ncand) {
            for (int cb = 0; cb < ncand; cb += 32) {
                int j = ncand - 1 - cb - lane;   // lane 0 = highest affinity in chunk
                bool has = (j >= 0);
                int rru = 0, rrv = 0;
                unsigned ab = 0;
                if (has) {
                    unsigned pr = croots[j];
                    rru = (int)(pr & 0xffffu);
                    rrv = (int)(pr >> 16);
                    ab  = caff[j];
                    // re-climb to current roots (filter roots already compressed)
                    int p = parent[rru];
                    while (p != rru) { rru = p; p = parent[rru]; }
                    p = parent[rrv];
                    while (p != rrv) { rrv = p; p = parent[rrv]; }
                }
                bool cc = has && (rru != rrv);
                unsigned cand = __ballot_sync(FULLM, cc);
                if (!cand) continue;

                // fast path: single candidate -> no conflicts possible
                if (__popc(cand) == 1) {
                    if (cc) {
                        unsigned iu = info[rru], iv2 = info[rrv];
                        int su = (int)(iu & 0xffffu), sv = (int)(iv2 & 0xffffu);
                        acc += (double)((int)(iu >> 16) * (int)(iv2 >> 16))
                             * (double)__uint_as_float(ab);
                        int big   = (su >= sv) ? rru : rrv;
                        int small = rru + rrv - big;
                        parent[small] = (unsigned short)big;
                        info[big] = iu + iv2;
                    }
                    __syncwarp(FULLM);
                    nmerges += 1;
                    if (nmerges == NN - 1) {
                        if (lane == 0) misc[0] = 1;
                        break;
                    }
                    continue;
                }

                unsigned prio = 32u - (unsigned)lane;   // higher = higher affinity
                unsigned h1 = 0, h2 = 0;
                if (cc) {
                    h1 = (unsigned)rru & (NBUCK - 1);
                    h2 = (unsigned)rrv & (NBUCK - 1);
                    atomicMax(&hist[h1], prio);
                    atomicMax(&hist[h2], prio);
                }
                __syncwarp(FULLM);
                bool par = cc && (hist[h1] == prio) && (hist[h2] == prio);
                unsigned parmask = __ballot_sync(FULLM, par);

                if (par) {   // conflict-free winners merge concurrently
                    unsigned iu = info[rru], iv2 = info[rrv];
                    int su = (int)(iu & 0xffffu), sv = (int)(iv2 & 0xffffu);
                    acc += (double)((int)(iu >> 16) * (int)(iv2 >> 16))
                         * (double)__uint_as_float(ab);
                    int big   = (su >= sv) ? rru : rrv;
                    int small = rru + rrv - big;
                    parent[small] = (unsigned short)big;
                    info[big] = iu + iv2;   // packed u16 adds, no carry (<=16384)
                }
                __syncwarp(FULLM);
                nmerges += __popc(parmask);

                // serial fallback, descending affinity = ascending lane
                unsigned def = cand & ~parmask;
                int sm = 0;
                while (def) {
                    int i = __ffs(def) - 1;
                    def &= def - 1;
                    int au = __shfl_sync(FULLM, rru, i);
                    int av = __shfl_sync(FULLM, rrv, i);
                    unsigned ab2 = __shfl_sync(FULLM, ab, i);
                    if (lane == 0) {
                        int p = parent[au];
                        while (p != au) { au = p; p = parent[au]; }
                        p = parent[av];
                        while (p != av) { av = p; p = parent[av]; }
                        if (au != av) {
                            unsigned iu = info[au], iv2 = info[av];
                            int su = (int)(iu & 0xffffu), sv = (int)(iv2 & 0xffffu);
                            acc += (double)((int)(iu >> 16) * (int)(iv2 >> 16))
                                 * (double)__uint_as_float(ab2);
                            int big   = (su >= sv) ? au : av;
                            int small = au + av - big;
                            parent[small] = (unsigned short)big;
                            info[big] = iu + iv2;
                            sm++;
                        }
                    }
                }
                nmerges += __shfl_sync(FULLM, sm, 0);

                if (cc) { hist[h1] = 0; hist[h2] = 0; }   // reset claim slots
                __syncwarp(FULLM);

                if (nmerges == NN - 1) {                  // MST complete
                    if (lane == 0) misc[0] = 1;
                    break;
                }
            }
        }
        __syncthreads();
        if (misc[0]) break;   // remaining edges contribute 0
    }

    // ---- final reduction (warp 0) ----
    if (wid == 0) {
        #pragma unroll
        for (int o = 16; o; o >>= 1)
            acc += __shfl_down_sync(FULLM, acc, o);
        if (lane == 0) {
            unsigned long long pairs = 0;
            for (int l = 1; l < 64; l++) {
                unsigned long long n = labcnt[l];
                pairs += n * (n - 1) / 2;
            }
            g_loss[b] = 0.5 * ((double)pairs - acc);
        }
    }
}

__global__ void finalize_kernel(float* out) {
    out[0] = (float)(g_loss[0] + g_loss[1]);
}

// ---------------- launch -------------------------------------------------
extern "C" void kernel_launch(void* const* d_in, const int* in_sizes, int n_in,
                              void* d_out, int out_size) {
    const float* aff = (const float*)d_in[0];
    const void*  gt  = d_in[1];
    (void)in_sizes; (void)n_in; (void)out_size;

    cudaFuncSetAttribute(malis_kernel,
                         cudaFuncAttributeMaxDynamicSharedMemorySize, SMEM_BYTES);
    malis_kernel<<<BB, 1024, SMEM_BYTES>>>(aff, gt);
    finalize_kernel<<<1, 1>>>((float*)d_out);
}

// round 17
// speedup vs baseline: 1.2198x; 1.0014x over previous
#include <cuda_runtime.h>
#include <cuda_bf16.h>

// Problem constants
#define HH 128
#define WW 128
#define NN (HH*WW)          // 16384 nodes per batch
#define EE (2*NN)           // 32768 edges per batch
#define BB 2
#define NBUCK 4096
#define WWIN 1024           // filter window (1 edge per thread)
#define FULLM 0xffffffffu

// ---------------- device globals (no allocation allowed) ----------------
__device__ unsigned long long g_sorted[BB][EE];   // (aff_bits<<32)|edge_idx, ascending
__device__ double g_loss[BB];

// Shared layout (dynamic), u32 first:
//   u32 info [NN]        64KB  (size | nz<<16)
//   u32 hist [NBUCK]     16KB  (sort cursors, then epoch-claim table)
//   u32 offs [NBUCK+1]   16KB
//   u32 warp_sums[32], labcnt[64], misc[4]
//   u32 caff  [WWIN]      4KB  (compacted candidate affinities)
//   u32 croots[WWIN]      4KB  (compacted candidate roots, ru|rv<<16)
//   u16 parent[NN]       32KB
#define SMEM_BYTES ((NN + NBUCK + (NBUCK+1) + 32 + 64 + 4 + WWIN + WWIN) * 4 + NN * 2)

extern __shared__ unsigned char smem_raw[];

__global__ void __launch_bounds__(1024) malis_kernel(const float* __restrict__ aff,
                                                     const void* __restrict__ gt) {
    int b    = blockIdx.x;
    int tid  = threadIdx.x;
    int lane = tid & 31;
    int wid  = tid >> 5;

    unsigned* info      = (unsigned*)smem_raw;
    unsigned* hist      = info + NN;
    unsigned* offs      = hist + NBUCK;
    unsigned* warp_sums = offs + NBUCK + 1;
    unsigned* labcnt    = warp_sums + 32;
    unsigned* misc      = labcnt + 64;           // [0]=detect/done  [1]=ncand
    unsigned* caff      = misc + 4;
    unsigned* croots    = caff + WWIN;
    unsigned short* parent = (unsigned short*)(croots + WWIN);

    // ---- detect int64 vs int32 groundtruth (labels < 64 -> odd words zero) ----
    if (tid == 0) misc[0] = 0;
    for (int i = tid; i < 64; i += 1024) labcnt[i] = 0;
    __syncthreads();
    {
        const int* g32 = (const int*)gt;
        if (g32[2 * tid + 1]) atomicOr(&misc[0], 1u);
    }
    __syncthreads();
    int is64 = (misc[0] == 0);

    // ---- init union-find + label histogram ----
    for (int n = tid; n < NN; n += 1024) {
        int l = is64 ? (int)((const long long*)gt)[b * NN + n]
                     : ((const int*)gt)[b * NN + n];
        parent[n] = (unsigned short)n;
        info[n]   = 1u | ((l != 0) ? (1u << 16) : 0u);
        if (l) atomicAdd(&labcnt[l], 1u);
    }

    // ---- bucket sort of edges (ascending by (aff_bits, idx)) ----
    const float* a = aff + b * EE;
    for (int i = tid; i < NBUCK; i += 1024) hist[i] = 0;
    __syncthreads();

    for (int e = tid; e < EE; e += 1024) {
        int bk = min(NBUCK - 1, (int)(a[e] * (float)NBUCK));
        atomicAdd(&hist[bk], 1u);
    }
    __syncthreads();

    // exclusive scan of hist[4096], 4 buckets per thread
    unsigned s0 = hist[4*tid], s1 = hist[4*tid+1], s2 = hist[4*tid+2], s3 = hist[4*tid+3];
    unsigned tsum = s0 + s1 + s2 + s3;
    unsigned inc = tsum;
    #pragma unroll
    for (int o = 1; o < 32; o <<= 1) {
        unsigned v = __shfl_up_sync(FULLM, inc, o);
        if (lane >= o) inc += v;
    }
    if (lane == 31) warp_sums[wid] = inc;
    __syncthreads();
    if (tid < 32) {
        unsigned v = warp_sums[tid];
        unsigned iv = v;
        #pragma unroll
        for (int o = 1; o < 32; o <<= 1) {
            unsigned t2 = __shfl_up_sync(FULLM, iv, o);
            if (tid >= o) iv += t2;
        }
        warp_sums[tid] = iv - v;  // exclusive warp base
    }
    __syncthreads();
    unsigned base0 = warp_sums[wid] + inc - tsum;
    offs[4*tid]   = base0;
    offs[4*tid+1] = base0 + s0;
    offs[4*tid+2] = base0 + s0 + s1;
    offs[4*tid+3] = base0 + s0 + s1 + s2;
    __syncthreads();
    for (int i = tid; i < NBUCK; i += 1024) hist[i] = offs[i];  // scatter cursors
    if (tid == 0) offs[NBUCK] = EE;
    __syncthreads();

    unsigned long long* arr = g_sorted[b];
    for (int e = tid; e < EE; e += 1024) {
        float av = a[e];
        int bk = min(NBUCK - 1, (int)(av * (float)NBUCK));
        unsigned pos = atomicAdd(&hist[bk], 1u);
        arr[pos] = ((unsigned long long)__float_as_uint(av) << 32) | (unsigned)e;
    }
    __syncthreads();

    // reset hist -> epoch-claim table for the resolve phase
    for (int i = tid; i < NBUCK; i += 1024) hist[i] = 0;

    // per-bucket insertion sort (ascending)
    {
        unsigned my_off[4], nxt_off[4];
        #pragma unroll
        for (int q = 0; q < 4; q++) {
            int bk = tid + q * 1024;
            my_off[q] = offs[bk];
            nxt_off[q] = offs[bk + 1];
        }
        #pragma unroll
        for (int q = 0; q < 4; q++) {
            int s = (int)my_off[q], epos = (int)nxt_off[q];
            for (int k = s + 1; k < epos; k++) {
                unsigned long long key = arr[k];
                int j = k - 1;
                while (j >= s && arr[j] > key) { arr[j + 1] = arr[j]; j--; }
                arr[j + 1] = key;
            }
        }
    }
    if (tid == 0) misc[0] = 0;   // done flag
    __syncthreads();

    // ==== windowed Kruskal: block-parallel filter + warp-0 compacted resolve ====
    // per-merge contribution: tu*tv*a   (n_pos telescopes to sum_l C(n_l,2))
    double acc = 0.0;       // meaningful in warp 0 lanes
    int nmerges = 0;        // warp-uniform in warp 0
    unsigned epoch = 0;     // warp-uniform claim epoch (warp 0)

    for (int wbase = EE - WWIN; wbase >= 0; wbase -= WWIN) {
        // ---- filter: 1 edge per thread, finds with path halving (forest static) ----
        unsigned long long pk = arr[wbase + tid];
        unsigned idx = (unsigned)pk;
        int c  = (int)(idx >> 14);
        int uu = (int)(idx & (NN - 1));
        int vv = (c == 0) ? ((uu < NN - WW) ? uu + WW : -1)
                          : (((uu & (WW - 1)) != WW - 1) ? uu + 1 : -1);
        int ru = 0, rv = 0;
        bool cnd = false;
        if (vv >= 0) {
            int x = uu, p = parent[x];
            while (p != x) {
                int g2 = parent[p];
                parent[x] = (unsigned short)g2;
                x = g2; p = parent[x];
            }
            ru = x;
            x = vv; p = parent[x];
            while (p != x) {
                int g2 = parent[p];
                parent[x] = (unsigned short)g2;
                x = g2; p = parent[x];
            }
            rv = x;
            cnd = (ru != rv);
        }
        unsigned wmask = __ballot_sync(FULLM, cnd);
        if (lane == 0) warp_sums[wid] = __popc(wmask);
        __syncthreads();
        if (tid < 32) {
            unsigned v = warp_sums[tid], iv = v;
            #pragma unroll
            for (int o = 1; o < 32; o <<= 1) {
                unsigned t2 = __shfl_up_sync(FULLM, iv, o);
                if (tid >= o) iv += t2;
            }
            warp_sums[tid] = iv - v;
            if (tid == 31) misc[1] = iv;   // ncand
        }
        __syncthreads();
        int ncand = (int)misc[1];
        if (cnd) {
            int r = (int)warp_sums[wid] + __popc(wmask & ((1u << lane) - 1));
            croots[r] = (unsigned)ru | ((unsigned)rv << 16);
            caff[r]   = (unsigned)(pk >> 32);
        }
        __syncthreads();

        // ---- resolve: warp 0 only, descending affinity = descending rank ----
        if (wid == 0 && ncand) {
            for (int cb = 0; cb < ncand; cb += 32) {
                int j = ncand - 1 - cb - lane;   // lane 0 = highest affinity in chunk
                bool active = (j >= 0);
                int rru = 0, rrv = 0;
                unsigned ab = 0;
                if (active) {
                    unsigned pr = croots[j];
                    rru = (int)(pr & 0xffffu);
                    rrv = (int)(pr >> 16);
                    ab  = caff[j];
                }

                // up to 2 parallel claim rounds, then serial fallback
                unsigned def = 0;
                for (int round = 0; ; round++) {
                    if (active) {
                        int p = parent[rru];
                        while (p != rru) { rru = p; p = parent[rru]; }
                        p = parent[rrv];
                        while (p != rrv) { rrv = p; p = parent[rrv]; }
                        active = (rru != rrv);
                    }
                    unsigned cand = __ballot_sync(FULLM, active);
                    if (!cand) break;

                    // fast path: single candidate -> no conflicts possible
                    if (__popc(cand) == 1) {
                        if (active) {
                            unsigned iu = info[rru], iv2 = info[rrv];
                            int su = (int)(iu & 0xffffu), sv = (int)(iv2 & 0xffffu);
                            acc += (double)((int)(iu >> 16) * (int)(iv2 >> 16))
                                 * (double)__uint_as_float(ab);
                            int big   = (su >= sv) ? rru : rrv;
                            int small = rru + rrv - big;
                            parent[small] = (unsigned short)big;
                            info[big] = iu + iv2;
                        }
                        __syncwarp(FULLM);
                        nmerges += 1;
                        break;
                    }

                    // epoch-versioned claims: no slot resets needed
                    epoch++;
                    unsigned val = (epoch << 6) | (32u - (unsigned)lane);
                    unsigned h1 = 0, h2 = 0;
                    if (active) {
                        h1 = (unsigned)rru & (NBUCK - 1);
                        h2 = (unsigned)rrv & (NBUCK - 1);
                        atomicMax(&hist[h1], val);
                        atomicMax(&hist[h2], val);
                    }
                    __syncwarp(FULLM);
                    bool par = active && (hist[h1] == val) && (hist[h2] == val);
                    unsigned parmask = __ballot_sync(FULLM, par);

                    if (par) {   // conflict-free winners merge concurrently
                        unsigned iu = info[rru], iv2 = info[rrv];
                        int su = (int)(iu & 0xffffu), sv = (int)(iv2 & 0xffffu);
                        acc += (double)((int)(iu >> 16) * (int)(iv2 >> 16))
                             * (double)__uint_as_float(ab);
                        int big   = (su >= sv) ? rru : rrv;
                        int small = rru + rrv - big;
                        parent[small] = (unsigned short)big;
                        info[big] = iu + iv2;   // packed u16 adds, no carry (<=16384)
                        active = false;
                    }
                    // deferred republish fresh roots for possible serial phase
                    if (active) croots[j] = (unsigned)rru | ((unsigned)rrv << 16);
                    __syncwarp(FULLM);
                    nmerges += __popc(parmask);

                    if (nmerges == NN - 1) break;
                    if (round >= 1) {                   // bounded: go serial
                        def = __ballot_sync(FULLM, active);
                        break;
                    }
                }

                // serial fallback: lane 0, smem-based, descending affinity order
                if (def) {
                    int sm = 0;
                    if (lane == 0) {
                        unsigned d = def;
                        while (d) {
                            int i = __ffs(d) - 1;   // ascending lane = descending aff
                            d &= d - 1;
                            int jj = ncand - 1 - cb - i;
                            unsigned pr  = croots[jj];
                            unsigned ab2 = caff[jj];
                            int au = (int)(pr & 0xffffu);
                            int av = (int)(pr >> 16);
                            int p = parent[au];
                            while (p != au) { au = p; p = parent[au]; }
                            p = parent[av];
                            while (p != av) { av = p; p = parent[av]; }
                            if (au != av) {
                                unsigned iu = info[au], iv2 = info[av];
                                int su = (int)(iu & 0xffffu), sv = (int)(iv2 & 0xffffu);
                                acc += (double)((int)(iu >> 16) * (int)(iv2 >> 16))
                                     * (double)__uint_as_float(ab2);
                                int big   = (su >= sv) ? au : av;
                                int small = au + av - big;
                                parent[small] = (unsigned short)big;
                                info[big] = iu + iv2;
                                sm++;
                            }
                        }
                    }
                    nmerges += __shfl_sync(FULLM, sm, 0);
                    __syncwarp(FULLM);
                }

                if (nmerges == NN - 1) {                  // MST complete
                    if (lane == 0) misc[0] = 1;
                    break;
                }
            }
        }
        __syncthreads();
        if (misc[0]) break;   // remaining edges contribute 0
    }

    // ---- final reduction (warp 0) ----
    if (wid == 0) {
        #pragma unroll
        for (int o = 16; o; o >>= 1)
            acc += __shfl_down_sync(FULLM, acc, o);
        if (lane == 0) {
            unsigned long long pairs = 0;
            for (int l = 1; l < 64; l++) {
                unsigned long long n = labcnt[l];
                pairs += n * (n - 1) / 2;
            }
            g_loss[b] = 0.5 * ((double)pairs - acc);
        }
    }
}

__global__ void finalize_kernel(float* out) {
    out[0] = (float)(g_loss[0] + g_loss[1]);
}

// ---------------- launch -------------------------------------------------
extern "C" void kernel_launch(void* const* d_in, const int* in_sizes, int n_in,
                              void* d_out, int out_size) {
    const float* aff = (const float*)d_in[0];
    const void*  gt  = d_in[1];
    (void)in_sizes; (void)n_in; (void)out_size;

    cudaFuncSetAttribute(malis_kernel,
                         cudaFuncAttributeMaxDynamicSharedMemorySize, SMEM_BYTES);
    malis_kernel<<<BB, 1024, SMEM_BYTES>>>(aff, gt);
    finalize_kernel<<<1, 1>>>((float*)d_out);
}